// round 12
// baseline (speedup 1.0000x reference)
#include <cuda_runtime.h>
#include <cuda_fp16.h>
#include <cstdint>

// ============================================================================
// MultiHeadNet, R12: scheduling round. Per-head GEMM2->GEMM3 chains on 4
// worker streams (head passed as arg, per-head tile budgets), merging the
// GEMM2 tail into GEMM3 and shrinking empty-CTA launches. GEMM core = R11
// (128x256 tile, 64x64 warp tiles, HMMA fp16, ~512 MAC/cyc/SM pipe cap).
// ============================================================================

constexpr int BATCH  = 8192;
constexpr int NBITS  = 3;
constexpr int DFEAT  = 512;
constexpr int DBASE  = 1024;
constexpr int DH     = 1024;
constexpr int DOUT   = 512;
constexpr int NHEADS = 8;
constexpr int XSTRIDE = NBITS + DFEAT; // 515

// per-head 128-row tile budgets: mean rows = 8192*p^bits*(1-p)^(3-bits),
// p(bit)=0.3085 -> head0 ~2708, 1-bit ~1207, 2-bit ~538, 3-bit ~241.
// Budgets are >= +11 sigma above mean.
static const int HTILES[NHEADS] = {25, 13, 13, 8, 13, 8, 8, 5};

// ---------------- scratch (__device__ globals) -------------------------------
__device__ int g_counts[NHEADS];
__device__ int g_off[NHEADS];
__device__ int g_cursor[NHEADS];
__device__ int g_permsrc[BATCH];

__device__ __half g_x[(size_t)BATCH * DFEAT];            // original row order
__device__ __half g_b[(size_t)BATCH * DBASE];            // original row order
__device__ __half g_h[(size_t)BATCH * DH];               // permuted (per-head)
__device__ __half g_wbt[(size_t)DBASE * DFEAT];          // [N][K]
__device__ __half g_w1t[(size_t)NHEADS * DH * DBASE];    // [h][N][K]
__device__ __half g_w2t[(size_t)NHEADS * DOUT * DH];     // [h][N][K]

// ---------------- streams + events (host-side, static init) ------------------
static cudaStream_t s_side = nullptr, s_rt = nullptr, s_w[4] = {};
static cudaEvent_t s_fork = nullptr, s_ewb = nullptr, s_ew1 = nullptr,
                   s_ew2 = nullptr, s_ert = nullptr, s_eg1 = nullptr,
                   s_e3[NHEADS] = {};
static struct SideInit {
    SideInit() {
        cudaStreamCreateWithFlags(&s_side, cudaStreamNonBlocking);
        cudaStreamCreateWithFlags(&s_rt,   cudaStreamNonBlocking);
        for (int i = 0; i < 4; i++) cudaStreamCreateWithFlags(&s_w[i], cudaStreamNonBlocking);
        cudaEventCreateWithFlags(&s_fork, cudaEventDisableTiming);
        cudaEventCreateWithFlags(&s_ewb,  cudaEventDisableTiming);
        cudaEventCreateWithFlags(&s_ew1,  cudaEventDisableTiming);
        cudaEventCreateWithFlags(&s_ew2,  cudaEventDisableTiming);
        cudaEventCreateWithFlags(&s_ert,  cudaEventDisableTiming);
        cudaEventCreateWithFlags(&s_eg1,  cudaEventDisableTiming);
        for (int i = 0; i < NHEADS; i++) cudaEventCreateWithFlags(&s_e3[i], cudaEventDisableTiming);
    }
} s_side_init;

// ---------------- PTX helpers -------------------------------------------------
__device__ __forceinline__ uint32_t smem_u32(const void* p) {
    uint32_t a;
    asm("{ .reg .u64 t; cvta.to.shared.u64 t, %1; cvt.u32.u64 %0, t; }" : "=r"(a) : "l"(p));
    return a;
}
#define CP_ASYNC16(saddr, gptr) \
    asm volatile("cp.async.cg.shared.global [%0], [%1], 16;" :: "r"(saddr), "l"(gptr))
#define CP_COMMIT() asm volatile("cp.async.commit_group;" ::: "memory")
#define CP_WAIT1()  asm volatile("cp.async.wait_group 1;" ::: "memory")
#define CP_WAIT0()  asm volatile("cp.async.wait_group 0;" ::: "memory")

__device__ __forceinline__ uint32_t lds32(uint32_t saddr) {
    uint32_t v;
    asm volatile("ld.shared.b32 %0, [%1];" : "=r"(v) : "r"(saddr));
    return v;
}
__device__ __forceinline__ void mma16816(float* c, const uint32_t* a, const uint32_t* b) {
    asm volatile("mma.sync.aligned.m16n8k16.row.col.f32.f16.f16.f32 "
        "{%0,%1,%2,%3}, {%4,%5,%6,%7}, {%8,%9}, {%0,%1,%2,%3};"
        : "+f"(c[0]), "+f"(c[1]), "+f"(c[2]), "+f"(c[3])
        : "r"(a[0]), "r"(a[1]), "r"(a[2]), "r"(a[3]), "r"(b[0]), "r"(b[1]));
}

// ---------------- prep kernels -------------------------------------------------
__device__ __forceinline__ int head_of(const float* xr) {
    return (xr[0] > 0.5f ? 1 : 0) | (xr[1] > 0.5f ? 2 : 0) | (xr[2] > 0.5f ? 4 : 0);
}
__global__ void k_zeroc() {
    if (threadIdx.x < NHEADS) g_counts[threadIdx.x] = 0;
}
__global__ void k_count(const float* __restrict__ x) {
    __shared__ int hist[NHEADS];
    if (threadIdx.x < NHEADS) hist[threadIdx.x] = 0;
    __syncthreads();
    int b = blockIdx.x * blockDim.x + threadIdx.x;
    if (b < BATCH) atomicAdd(&hist[head_of(x + (size_t)b * XSTRIDE)], 1);
    __syncthreads();
    if (threadIdx.x < NHEADS) atomicAdd(&g_counts[threadIdx.x], hist[threadIdx.x]);
}
__global__ void k_scanzero() {
    if (threadIdx.x == 0) {
        int s = 0;
        for (int h = 0; h < NHEADS; h++) {
            int c = g_counts[h];
            g_off[h] = s; g_cursor[h] = s; s += c;
        }
    }
}
__global__ void k_fillperm(const float* __restrict__ x) {
    int b = blockIdx.x * blockDim.x + threadIdx.x;
    if (b >= BATCH) return;
    int pos = atomicAdd(&g_cursor[head_of(x + (size_t)b * XSTRIDE)], 1);
    g_permsrc[pos] = b;
}
__global__ void k_convert(const float* __restrict__ x) {
    int idx = (blockIdx.x * blockDim.x + threadIdx.x) * 2;
    if (idx >= BATCH * DFEAT) return;
    int b = idx / DFEAT, c = idx % DFEAT;
    const float* xr = x + (size_t)b * XSTRIDE + NBITS + c;
    *(__half2*)(g_x + (size_t)b * DFEAT + c) =
        __halves2half2(__float2half(xr[0]), __float2half(xr[1]));
}
__global__ void k_transpose(const float* __restrict__ in, __half* __restrict__ outp,
                            int R, int C) {
    __shared__ float t[32][33];
    int z = blockIdx.z;
    const float* src = in + (size_t)z * R * C;
    size_t ob = (size_t)z * R * C;
    int c0 = blockIdx.x * 32, r0 = blockIdx.y * 32;
    int tx = threadIdx.x, ty = threadIdx.y;
    #pragma unroll
    for (int i = 0; i < 32; i += 8)
        t[ty + i][tx] = src[(size_t)(r0 + ty + i) * C + c0 + tx];
    __syncthreads();
    #pragma unroll
    for (int i = 0; i < 32; i += 8)
        outp[ob + (size_t)(c0 + ty + i) * R + r0 + tx] = __float2half(t[tx][ty + i]);
}

// ---------------- HMMA grouped GEMM --------------------------------------------
// Block tile 128(M) x 256(N) x Kc=64. 8 warps, 2x4 grid of 64x64 warp tiles.
// 2-stage cp.async double buffer, smem pitch 144B, 1 CTA/SM. Head is a kernel
// argument (per-head launches); useCounts=0 -> dense over BATCH rows.
constexpr int KC = 64;
constexpr int BN = 256;
constexpr int PITCH = 144;
constexpr int A_PB = 128 * PITCH;                   // 18432
constexpr int B_PB = BN * PITCH;                    // 36864
constexpr int OFF_A = 0, OFF_B = A_PB;
constexpr int STAGE_B = A_PB + B_PB;                // 55296
constexpr int DSMEM_BYTES = 2 * STAGE_B + 1024;     // 111616

// CMODE 0: relu -> fp16 contiguous rows.  CMODE 1: fp32 scatter via permsrc.
// GATHER 1: A rows indexed by g_permsrc (GEMM2).
template<int CMODE, int GATHER>
__global__ __launch_bounds__(256, 1)
void gemm_hmma(const __half* __restrict__ A, const __half* __restrict__ B,
               const float* __restrict__ bias,
               __half* __restrict__ Ch, float* __restrict__ Cf,
               int K, int N, int useCounts, int head)
{
    extern __shared__ char dsm_raw[];
    __shared__ int s_rowidx[128];
    char* dsm = (char*)(((uintptr_t)dsm_raw + 1023) & ~(uintptr_t)1023);
    const uint32_t sbase = smem_u32(dsm);

    const int rowBeg = useCounts ? g_off[head] : 0;
    const int cnt    = useCounts ? g_counts[head] : BATCH;
    const int m0     = rowBeg + blockIdx.y * 128;
    if (m0 >= rowBeg + cnt) return;
    const int mValid = min(128, rowBeg + cnt - m0);
    const int n0  = blockIdx.x * BN;
    const int tid = threadIdx.x;
    const int wid  = tid >> 5;
    const int lane = tid & 31;
    const int NC = K / KC;

    if (GATHER) {
        if (tid < 128) {
            int p = m0 + tid;
            s_rowidx[tid] = g_permsrc[p < rowBeg + cnt ? p : rowBeg + cnt - 1];
        }
        __syncthreads();
    }

    // stage loader: A 1024 chunks + B 2048 chunks = 3072 / 256 thr = 12 iters
    auto load_stage = [&](int c) {
        const int kt = c * KC;
        const uint32_t sb = sbase + (c & 1) * STAGE_B;
        #pragma unroll
        for (int j = 0; j < 12; ++j) {
            int idx = j * 256 + tid;               // 0..3071
            const __half* gp;
            uint32_t dst;
            if (idx < 1024) {                      // A tile: 128 rows x 8 chunks
                int r = idx >> 3, q = idx & 7;
                dst = sb + OFF_A + (uint32_t)(r * PITCH + q * 16);
                int rowg = GATHER ? s_rowidx[r] : min(m0 + r, BATCH - 1);
                gp = A + (size_t)rowg * K + kt + q * 8;
            } else {                               // B tile: 256 rows x 8 chunks
                int t2 = idx - 1024;
                int r = t2 >> 3, q = t2 & 7;
                dst = sb + OFF_B + (uint32_t)(r * PITCH + q * 16);
                gp = B + ((size_t)head * N + n0 + r) * K + kt + q * 8;
            }
            CP_ASYNC16(dst, gp);
        }
    };

    load_stage(0); CP_COMMIT();

    // warp grid 2(Mrows) x 4(Ncols); warp tile 64x64
    const int wm = (wid >> 2) * 64;
    const int wn = (wid & 3) * 64;
    const int gid = lane >> 2;
    const int tig = lane & 3;

    float acc[4][8][4];
    #pragma unroll
    for (int mg = 0; mg < 4; mg++)
        #pragma unroll
        for (int ng = 0; ng < 8; ng++)
            #pragma unroll
            for (int v = 0; v < 4; v++) acc[mg][ng][v] = 0.0f;

    for (int c = 0; c < NC; ++c) {
        if (c + 1 < NC) load_stage(c + 1);
        CP_COMMIT();
        CP_WAIT1();
        __syncthreads();

        const uint32_t sb = sbase + (c & 1) * STAGE_B;
        const uint32_t sA = sb + OFF_A, sB = sb + OFF_B;

        #pragma unroll
        for (int kk = 0; kk < KC; kk += 16) {
            const uint32_t kb = (uint32_t)(kk * 2 + tig * 4);
            uint32_t af[4][4], bfr[8][2];
            #pragma unroll
            for (int mg = 0; mg < 4; mg++) {
                const uint32_t p0 = (uint32_t)((wm + mg * 16 + gid) * PITCH) + kb;
                af[mg][0] = lds32(sA + p0);
                af[mg][1] = lds32(sA + p0 + 8 * PITCH);
                af[mg][2] = lds32(sA + p0 + 16);
                af[mg][3] = lds32(sA + p0 + 8 * PITCH + 16);
            }
            #pragma unroll
            for (int ng = 0; ng < 8; ng++) {
                const uint32_t p0 = (uint32_t)((wn + ng * 8 + gid) * PITCH) + kb;
                bfr[ng][0] = lds32(sB + p0);
                bfr[ng][1] = lds32(sB + p0 + 16);
            }
            #pragma unroll
            for (int mg = 0; mg < 4; mg++)
                #pragma unroll
                for (int ng = 0; ng < 8; ng++)
                    mma16816(acc[mg][ng], af[mg], bfr[ng]);
        }
        __syncthreads();
    }
    CP_WAIT0();

    const float* bp = bias + (size_t)head * N + n0;
    #pragma unroll
    for (int mg = 0; mg < 4; mg++) {
        #pragma unroll
        for (int half = 0; half < 2; half++) {
            const int mrow = wm + mg * 16 + gid + half * 8;
            if (mrow >= mValid) continue;
            const int gm = m0 + mrow;
            #pragma unroll
            for (int ng = 0; ng < 8; ng++) {
                const int col = wn + ng * 8 + tig * 2;
                float v0 = acc[mg][ng][half * 2]     + __ldg(bp + col);
                float v1 = acc[mg][ng][half * 2 + 1] + __ldg(bp + col + 1);
                if (CMODE == 0) {
                    v0 = fmaxf(v0, 0.0f); v1 = fmaxf(v1, 0.0f);
                    size_t o = (size_t)gm * N + n0 + col;
                    *(__half2*)(Ch + o) = __halves2half2(__float2half(v0), __float2half(v1));
                } else {
                    const int orow = g_permsrc[gm];
                    *(float2*)(Cf + (size_t)orow * N + n0 + col) = make_float2(v0, v1);
                }
            }
        }
    }
}

// ---------------- host launcher -------------------------------------------------
extern "C" void kernel_launch(void* const* d_in, const int* in_sizes, int n_in,
                              void* d_out, int out_size)
{
    (void)in_sizes; (void)n_in; (void)out_size;
    const float* x   = (const float*)d_in[0];
    const float* Wb  = (const float*)d_in[1];
    const float* bb  = (const float*)d_in[2];
    const float* Wh1 = (const float*)d_in[3];
    const float* bh1 = (const float*)d_in[4];
    const float* Wh2 = (const float*)d_in[5];
    const float* bh2 = (const float*)d_in[6];
    float* out = (float*)d_out;

    void *p_x, *p_b, *p_h, *p_wbt, *p_w1t, *p_w2t;
    cudaGetSymbolAddress(&p_x, g_x);
    cudaGetSymbolAddress(&p_b, g_b);
    cudaGetSymbolAddress(&p_h, g_h);
    cudaGetSymbolAddress(&p_wbt, g_wbt);
    cudaGetSymbolAddress(&p_w1t, g_w1t);
    cudaGetSymbolAddress(&p_w2t, g_w2t);

    cudaFuncSetAttribute((const void*)gemm_hmma<0,0>, cudaFuncAttributeMaxDynamicSharedMemorySize, DSMEM_BYTES);
    cudaFuncSetAttribute((const void*)gemm_hmma<0,1>, cudaFuncAttributeMaxDynamicSharedMemorySize, DSMEM_BYTES);
    cudaFuncSetAttribute((const void*)gemm_hmma<1,0>, cudaFuncAttributeMaxDynamicSharedMemorySize, DSMEM_BYTES);

    // ---- fork ----
    cudaEventRecord(s_fork, 0);
    cudaStreamWaitEvent(s_side, s_fork, 0);
    cudaStreamWaitEvent(s_rt,   s_fork, 0);

    // side1: weight transposes
    k_transpose<<<dim3(DBASE / 32, DFEAT / 32, 1), dim3(32, 8), 0, s_side>>>(
        Wb, (__half*)p_wbt, DFEAT, DBASE);
    cudaEventRecord(s_ewb, s_side);
    k_transpose<<<dim3(DH / 32, DBASE / 32, NHEADS), dim3(32, 8), 0, s_side>>>(
        Wh1, (__half*)p_w1t, DBASE, DH);
    cudaEventRecord(s_ew1, s_side);
    k_transpose<<<dim3(DOUT / 32, DH / 32, NHEADS), dim3(32, 8), 0, s_side>>>(
        Wh2, (__half*)p_w2t, DH, DOUT);
    cudaEventRecord(s_ew2, s_side);

    // side2: routing (index-only)
    k_zeroc<<<1, 32, 0, s_rt>>>();
    k_count<<<BATCH / 256, 256, 0, s_rt>>>(x);
    k_scanzero<<<1, 32, 0, s_rt>>>();
    k_fillperm<<<BATCH / 256, 256, 0, s_rt>>>(x);
    cudaEventRecord(s_ert, s_rt);

    // main: convert -> GEMM1
    k_convert<<<(BATCH * DFEAT / 2 + 255) / 256, 256>>>(x);
    cudaStreamWaitEvent(0, s_ewb, 0);
    gemm_hmma<0,0><<<dim3(DBASE / BN, BATCH / 128, 1), 256, DSMEM_BYTES>>>(
        (const __half*)p_x, (const __half*)p_wbt,
        bb, (__half*)p_b, nullptr, DFEAT, DBASE, 0, 0);
    cudaEventRecord(s_eg1, 0);

    // per-head GEMM2 -> GEMM3 chains on 4 worker streams
    for (int h = 0; h < NHEADS; ++h) {
        cudaStream_t st = s_w[h & 3];
        cudaStreamWaitEvent(st, s_eg1, 0);
        cudaStreamWaitEvent(st, s_ert, 0);
        cudaStreamWaitEvent(st, s_ew1, 0);
        gemm_hmma<0,1><<<dim3(DH / BN, HTILES[h], 1), 256, DSMEM_BYTES, st>>>(
            (const __half*)p_b, (const __half*)p_w1t,
            bh1, (__half*)p_h, nullptr, DBASE, DH, 1, h);
        cudaStreamWaitEvent(st, s_ew2, 0);
        gemm_hmma<1,0><<<dim3(DOUT / BN, HTILES[h], 1), 256, DSMEM_BYTES, st>>>(
            (const __half*)p_h, (const __half*)p_w2t,
            bh2, nullptr, out, DH, DOUT, 1, h);
        cudaEventRecord(s_e3[h], st);
    }
    // join all workers back to the main stream
    for (int h = 0; h < NHEADS; ++h)
        cudaStreamWaitEvent(0, s_e3[h], 0);
}

// round 13
// speedup vs baseline: 1.4302x; 1.4302x over previous
#include <cuda_runtime.h>
#include <cuda_fp16.h>
#include <cstdint>

// ============================================================================
// MultiHeadNet, R13: R11 structure (wide single-grid GEMMs, side streams)
// + KC=128 (half the barrier count per CTA) + device-built compact tile map
// for the grouped GEMMs (no empty-CTA dispatch). HMMA fp16 core,
// ~512 MAC/cyc/SM pipe cap. rel_err ~5e-4 unchanged.
// ============================================================================

constexpr int BATCH  = 8192;
constexpr int NBITS  = 3;
constexpr int DFEAT  = 512;
constexpr int DBASE  = 1024;
constexpr int DH     = 1024;
constexpr int DOUT   = 512;
constexpr int NHEADS = 8;
constexpr int XSTRIDE = NBITS + DFEAT; // 515
constexpr int MAXTILES = 76;           // >= worst-case sum ceil(cnt_h/128) = 72

// ---------------- scratch (__device__ globals) -------------------------------
__device__ int g_counts[NHEADS];
__device__ int g_off[NHEADS];
__device__ int g_cursor[NHEADS];
__device__ int g_permsrc[BATCH];
__device__ int g_tilemap[MAXTILES];    // (head<<16) | mtile
__device__ int g_ntiles;

__device__ __half g_x[(size_t)BATCH * DFEAT];            // original row order
__device__ __half g_b[(size_t)BATCH * DBASE];            // original row order
__device__ __half g_h[(size_t)BATCH * DH];               // permuted (per-head)
__device__ __half g_wbt[(size_t)DBASE * DFEAT];          // [N][K]
__device__ __half g_w1t[(size_t)NHEADS * DH * DBASE];    // [h][N][K]
__device__ __half g_w2t[(size_t)NHEADS * DOUT * DH];     // [h][N][K]

// ---------------- streams + events (host-side, static init) ------------------
static cudaStream_t s_side = nullptr, s_rt = nullptr;
static cudaEvent_t s_fork = nullptr, s_ewb = nullptr, s_ew1 = nullptr,
                   s_ew2 = nullptr, s_ert = nullptr;
static struct SideInit {
    SideInit() {
        cudaStreamCreateWithFlags(&s_side, cudaStreamNonBlocking);
        cudaStreamCreateWithFlags(&s_rt,   cudaStreamNonBlocking);
        cudaEventCreateWithFlags(&s_fork, cudaEventDisableTiming);
        cudaEventCreateWithFlags(&s_ewb,  cudaEventDisableTiming);
        cudaEventCreateWithFlags(&s_ew1,  cudaEventDisableTiming);
        cudaEventCreateWithFlags(&s_ew2,  cudaEventDisableTiming);
        cudaEventCreateWithFlags(&s_ert,  cudaEventDisableTiming);
    }
} s_side_init;

// ---------------- PTX helpers -------------------------------------------------
__device__ __forceinline__ uint32_t smem_u32(const void* p) {
    uint32_t a;
    asm("{ .reg .u64 t; cvta.to.shared.u64 t, %1; cvt.u32.u64 %0, t; }" : "=r"(a) : "l"(p));
    return a;
}
#define CP_ASYNC16(saddr, gptr) \
    asm volatile("cp.async.cg.shared.global [%0], [%1], 16;" :: "r"(saddr), "l"(gptr))
#define CP_COMMIT() asm volatile("cp.async.commit_group;" ::: "memory")
#define CP_WAIT1()  asm volatile("cp.async.wait_group 1;" ::: "memory")
#define CP_WAIT0()  asm volatile("cp.async.wait_group 0;" ::: "memory")

__device__ __forceinline__ uint32_t lds32(uint32_t saddr) {
    uint32_t v;
    asm volatile("ld.shared.b32 %0, [%1];" : "=r"(v) : "r"(saddr));
    return v;
}
__device__ __forceinline__ void mma16816(float* c, const uint32_t* a, const uint32_t* b) {
    asm volatile("mma.sync.aligned.m16n8k16.row.col.f32.f16.f16.f32 "
        "{%0,%1,%2,%3}, {%4,%5,%6,%7}, {%8,%9}, {%0,%1,%2,%3};"
        : "+f"(c[0]), "+f"(c[1]), "+f"(c[2]), "+f"(c[3])
        : "r"(a[0]), "r"(a[1]), "r"(a[2]), "r"(a[3]), "r"(b[0]), "r"(b[1]));
}

// ---------------- prep kernels -------------------------------------------------
__device__ __forceinline__ int head_of(const float* xr) {
    return (xr[0] > 0.5f ? 1 : 0) | (xr[1] > 0.5f ? 2 : 0) | (xr[2] > 0.5f ? 4 : 0);
}
__global__ void k_zeroc() {
    if (threadIdx.x < NHEADS) g_counts[threadIdx.x] = 0;
}
__global__ void k_count(const float* __restrict__ x) {
    __shared__ int hist[NHEADS];
    if (threadIdx.x < NHEADS) hist[threadIdx.x] = 0;
    __syncthreads();
    int b = blockIdx.x * blockDim.x + threadIdx.x;
    if (b < BATCH) atomicAdd(&hist[head_of(x + (size_t)b * XSTRIDE)], 1);
    __syncthreads();
    if (threadIdx.x < NHEADS) atomicAdd(&g_counts[threadIdx.x], hist[threadIdx.x]);
}
// scan offsets + build compact (head, mtile) tile map
__global__ void k_scanzero() {
    if (threadIdx.x == 0) {
        int s = 0, t = 0;
        for (int h = 0; h < NHEADS; h++) {
            int c = g_counts[h];
            g_off[h] = s; g_cursor[h] = s; s += c;
            int nt = (c + 127) / 128;
            for (int m = 0; m < nt && t < MAXTILES; m++)
                g_tilemap[t++] = (h << 16) | m;
        }
        g_ntiles = t;
    }
}
__global__ void k_fillperm(const float* __restrict__ x) {
    int b = blockIdx.x * blockDim.x + threadIdx.x;
    if (b >= BATCH) return;
    int pos = atomicAdd(&g_cursor[head_of(x + (size_t)b * XSTRIDE)], 1);
    g_permsrc[pos] = b;
}
__global__ void k_convert(const float* __restrict__ x) {
    int idx = (blockIdx.x * blockDim.x + threadIdx.x) * 2;
    if (idx >= BATCH * DFEAT) return;
    int b = idx / DFEAT, c = idx % DFEAT;
    const float* xr = x + (size_t)b * XSTRIDE + NBITS + c;
    *(__half2*)(g_x + (size_t)b * DFEAT + c) =
        __halves2half2(__float2half(xr[0]), __float2half(xr[1]));
}
__global__ void k_transpose(const float* __restrict__ in, __half* __restrict__ outp,
                            int R, int C) {
    __shared__ float t[32][33];
    int z = blockIdx.z;
    const float* src = in + (size_t)z * R * C;
    size_t ob = (size_t)z * R * C;
    int c0 = blockIdx.x * 32, r0 = blockIdx.y * 32;
    int tx = threadIdx.x, ty = threadIdx.y;
    #pragma unroll
    for (int i = 0; i < 32; i += 8)
        t[ty + i][tx] = src[(size_t)(r0 + ty + i) * C + c0 + tx];
    __syncthreads();
    #pragma unroll
    for (int i = 0; i < 32; i += 8)
        outp[ob + (size_t)(c0 + ty + i) * R + r0 + tx] = __float2half(t[tx][ty + i]);
}

// ---------------- HMMA grouped GEMM --------------------------------------------
// Block tile 128(M) x 256(N) x Kc=128. 8 warps, 2x4 grid of 64x64 warp tiles.
// 2-stage cp.async double buffer, smem pitch 272B (68 words; 68%32=4 ->
// fragment reads hit banks 4*gid+tig, all distinct). 1 CTA/SM.
constexpr int KC = 128;
constexpr int BN = 256;
constexpr int PITCH = 272;                          // 256 data + 16 pad bytes
constexpr int A_PB = 128 * PITCH;                   // 34816
constexpr int B_PB = BN * PITCH;                    // 69632
constexpr int OFF_A = 0, OFF_B = A_PB;
constexpr int STAGE_B = A_PB + B_PB;                // 104448
constexpr int DSMEM_BYTES = 2 * STAGE_B + 1024;     // 209920

// MODE 0: dense over BATCH rows (GEMM1).  MODE 1: tile-mapped grouped.
// CMODE 0: relu -> fp16 contiguous rows.  CMODE 1: fp32 scatter via permsrc.
// GATHER 1: A rows indexed by g_permsrc (GEMM2).
template<int CMODE, int GATHER, int MODE>
__global__ __launch_bounds__(256, 1)
void gemm_hmma(const __half* __restrict__ A, const __half* __restrict__ B,
               const float* __restrict__ bias,
               __half* __restrict__ Ch, float* __restrict__ Cf,
               int K, int N)
{
    extern __shared__ char dsm_raw[];
    __shared__ int s_rowidx[128];
    char* dsm = (char*)(((uintptr_t)dsm_raw + 1023) & ~(uintptr_t)1023);
    const uint32_t sbase = smem_u32(dsm);

    int head, m0, mValid, rowEnd;
    if (MODE == 0) {
        head = 0;
        m0 = blockIdx.y * 128;
        mValid = 128;
        rowEnd = BATCH;
    } else {
        if ((int)blockIdx.y >= g_ntiles) return;
        int e = g_tilemap[blockIdx.y];
        head = e >> 16;
        int mtile = e & 0xFFFF;
        int rowBeg = g_off[head];
        int cnt = g_counts[head];
        m0 = rowBeg + mtile * 128;
        mValid = min(128, cnt - mtile * 128);
        rowEnd = rowBeg + cnt;
    }
    const int n0  = blockIdx.x * BN;
    const int tid = threadIdx.x;
    const int wid  = tid >> 5;
    const int lane = tid & 31;
    const int NC = K / KC;

    if (GATHER) {
        if (tid < 128) {
            int p = m0 + tid;
            s_rowidx[tid] = g_permsrc[p < rowEnd ? p : rowEnd - 1];
        }
        __syncthreads();
    }

    // stage loader: A 2048 chunks + B 4096 chunks = 6144 / 256 thr = 24 iters
    auto load_stage = [&](int c) {
        const int kt = c * KC;
        const uint32_t sb = sbase + (c & 1) * STAGE_B;
        #pragma unroll
        for (int j = 0; j < 24; ++j) {
            int idx = j * 256 + tid;               // 0..6143
            const __half* gp;
            uint32_t dst;
            if (idx < 2048) {                      // A: 128 rows x 16 chunks
                int r = idx >> 4, q = idx & 15;
                dst = sb + OFF_A + (uint32_t)(r * PITCH + q * 16);
                int rowg = GATHER ? s_rowidx[r] : min(m0 + r, BATCH - 1);
                gp = A + (size_t)rowg * K + kt + q * 8;
            } else {                               // B: 256 rows x 16 chunks
                int t2 = idx - 2048;
                int r = t2 >> 4, q = t2 & 15;
                dst = sb + OFF_B + (uint32_t)(r * PITCH + q * 16);
                gp = B + ((size_t)head * N + n0 + r) * K + kt + q * 8;
            }
            CP_ASYNC16(dst, gp);
        }
    };

    load_stage(0); CP_COMMIT();

    // warp grid 2(Mrows) x 4(Ncols); warp tile 64x64
    const int wm = (wid >> 2) * 64;
    const int wn = (wid & 3) * 64;
    const int gid = lane >> 2;
    const int tig = lane & 3;

    float acc[4][8][4];
    #pragma unroll
    for (int mg = 0; mg < 4; mg++)
        #pragma unroll
        for (int ng = 0; ng < 8; ng++)
            #pragma unroll
            for (int v = 0; v < 4; v++) acc[mg][ng][v] = 0.0f;

    for (int c = 0; c < NC; ++c) {
        if (c + 1 < NC) load_stage(c + 1);
        CP_COMMIT();
        CP_WAIT1();
        __syncthreads();

        const uint32_t sb = sbase + (c & 1) * STAGE_B;
        const uint32_t sA = sb + OFF_A, sB = sb + OFF_B;

        #pragma unroll
        for (int kk = 0; kk < KC; kk += 16) {
            const uint32_t kb = (uint32_t)(kk * 2 + tig * 4);
            uint32_t af[4][4], bfr[8][2];
            #pragma unroll
            for (int mg = 0; mg < 4; mg++) {
                const uint32_t p0 = (uint32_t)((wm + mg * 16 + gid) * PITCH) + kb;
                af[mg][0] = lds32(sA + p0);
                af[mg][1] = lds32(sA + p0 + 8 * PITCH);
                af[mg][2] = lds32(sA + p0 + 16);
                af[mg][3] = lds32(sA + p0 + 8 * PITCH + 16);
            }
            #pragma unroll
            for (int ng = 0; ng < 8; ng++) {
                const uint32_t p0 = (uint32_t)((wn + ng * 8 + gid) * PITCH) + kb;
                bfr[ng][0] = lds32(sB + p0);
                bfr[ng][1] = lds32(sB + p0 + 16);
            }
            #pragma unroll
            for (int mg = 0; mg < 4; mg++)
                #pragma unroll
                for (int ng = 0; ng < 8; ng++)
                    mma16816(acc[mg][ng], af[mg], bfr[ng]);
        }
        __syncthreads();
    }
    CP_WAIT0();

    const float* bp = bias + (size_t)head * N + n0;
    #pragma unroll
    for (int mg = 0; mg < 4; mg++) {
        #pragma unroll
        for (int half = 0; half < 2; half++) {
            const int mrow = wm + mg * 16 + gid + half * 8;
            if (mrow >= mValid) continue;
            const int gm = m0 + mrow;
            #pragma unroll
            for (int ng = 0; ng < 8; ng++) {
                const int col = wn + ng * 8 + tig * 2;
                float v0 = acc[mg][ng][half * 2]     + __ldg(bp + col);
                float v1 = acc[mg][ng][half * 2 + 1] + __ldg(bp + col + 1);
                if (CMODE == 0) {
                    v0 = fmaxf(v0, 0.0f); v1 = fmaxf(v1, 0.0f);
                    size_t o = (size_t)gm * N + n0 + col;
                    *(__half2*)(Ch + o) = __halves2half2(__float2half(v0), __float2half(v1));
                } else {
                    const int orow = g_permsrc[gm];
                    *(float2*)(Cf + (size_t)orow * N + n0 + col) = make_float2(v0, v1);
                }
            }
        }
    }
}

// ---------------- host launcher -------------------------------------------------
extern "C" void kernel_launch(void* const* d_in, const int* in_sizes, int n_in,
                              void* d_out, int out_size)
{
    (void)in_sizes; (void)n_in; (void)out_size;
    const float* x   = (const float*)d_in[0];
    const float* Wb  = (const float*)d_in[1];
    const float* bb  = (const float*)d_in[2];
    const float* Wh1 = (const float*)d_in[3];
    const float* bh1 = (const float*)d_in[4];
    const float* Wh2 = (const float*)d_in[5];
    const float* bh2 = (const float*)d_in[6];
    float* out = (float*)d_out;

    void *p_x, *p_b, *p_h, *p_wbt, *p_w1t, *p_w2t;
    cudaGetSymbolAddress(&p_x, g_x);
    cudaGetSymbolAddress(&p_b, g_b);
    cudaGetSymbolAddress(&p_h, g_h);
    cudaGetSymbolAddress(&p_wbt, g_wbt);
    cudaGetSymbolAddress(&p_w1t, g_w1t);
    cudaGetSymbolAddress(&p_w2t, g_w2t);

    cudaFuncSetAttribute((const void*)gemm_hmma<0,0,0>, cudaFuncAttributeMaxDynamicSharedMemorySize, DSMEM_BYTES);
    cudaFuncSetAttribute((const void*)gemm_hmma<0,1,1>, cudaFuncAttributeMaxDynamicSharedMemorySize, DSMEM_BYTES);
    cudaFuncSetAttribute((const void*)gemm_hmma<1,0,1>, cudaFuncAttributeMaxDynamicSharedMemorySize, DSMEM_BYTES);

    // ---- fork ----
    cudaEventRecord(s_fork, 0);
    cudaStreamWaitEvent(s_side, s_fork, 0);
    cudaStreamWaitEvent(s_rt,   s_fork, 0);

    // side1: weight transposes
    k_transpose<<<dim3(DBASE / 32, DFEAT / 32, 1), dim3(32, 8), 0, s_side>>>(
        Wb, (__half*)p_wbt, DFEAT, DBASE);
    cudaEventRecord(s_ewb, s_side);
    k_transpose<<<dim3(DH / 32, DBASE / 32, NHEADS), dim3(32, 8), 0, s_side>>>(
        Wh1, (__half*)p_w1t, DBASE, DH);
    cudaEventRecord(s_ew1, s_side);
    k_transpose<<<dim3(DOUT / 32, DH / 32, NHEADS), dim3(32, 8), 0, s_side>>>(
        Wh2, (__half*)p_w2t, DH, DOUT);
    cudaEventRecord(s_ew2, s_side);

    // side2: routing (index-only; overlaps convert + GEMM1)
    k_zeroc<<<1, 32, 0, s_rt>>>();
    k_count<<<BATCH / 256, 256, 0, s_rt>>>(x);
    k_scanzero<<<1, 32, 0, s_rt>>>();
    k_fillperm<<<BATCH / 256, 256, 0, s_rt>>>(x);
    cudaEventRecord(s_ert, s_rt);

    // main: convert, then the three GEMMs
    k_convert<<<(BATCH * DFEAT / 2 + 255) / 256, 256>>>(x);

    cudaStreamWaitEvent(0, s_ewb, 0);
    gemm_hmma<0,0,0><<<dim3(DBASE / BN, BATCH / 128, 1), 256, DSMEM_BYTES>>>(
        (const __half*)p_x, (const __half*)p_wbt,
        bb, (__half*)p_b, nullptr, DFEAT, DBASE);

    cudaStreamWaitEvent(0, s_ert, 0);
    cudaStreamWaitEvent(0, s_ew1, 0);
    gemm_hmma<0,1,1><<<dim3(DH / BN, MAXTILES, 1), 256, DSMEM_BYTES>>>(
        (const __half*)p_b, (const __half*)p_w1t,
        bh1, (__half*)p_h, nullptr, DBASE, DH);

    cudaStreamWaitEvent(0, s_ew2, 0);
    gemm_hmma<1,0,1><<<dim3(DOUT / BN, MAXTILES, 1), 256, DSMEM_BYTES>>>(
        (const __half*)p_h, (const __half*)p_w2t,
        bh2, nullptr, out, DH, DOUT);
}